// round 3
// baseline (speedup 1.0000x reference)
#include <cuda_runtime.h>
#include <math_constants.h>

#define BB   4
#define NN   8192
#define SS   2048
#define D1   128
#define D2   256
#define CIN  384     // D2 + D1
#define CMID 256
#define COUT 256

// ---------------- scratch (device globals, no allocs) ----------------
__device__ float g_X[BB * CIN * NN];    // concat input [b][c][n]; reused as Y2 [b][256][n]
__device__ float g_Y[BB * CMID * NN];   // GEMM1 output [b][o][n]
__device__ float g_w[BB * NN * 3];
__device__ int   g_idx[BB * NN * 3];
__device__ float g_scale[CMID];
__device__ float g_shift[CMID];

// ---------------- 3-NN: warp per query point ----------------
__device__ __forceinline__ void top3_insert(float d, int i,
                                            float& d0, float& d1, float& d2v,
                                            int& i0, int& i1, int& i2) {
    bool b2 = (d < d2v) || (d == d2v && i < i2);
    if (!b2) return;
    bool b1 = (d < d1) || (d == d1 && i < i1);
    bool b0 = (d < d0) || (d == d0 && i < i0);
    if (b0)      { d2v = d1; i2 = i1; d1 = d0; i1 = i0; d0 = d;  i0 = i; }
    else if (b1) { d2v = d1; i2 = i1; d1 = d;  i1 = i; }
    else         { d2v = d;  i2 = i; }
}

__global__ void __launch_bounds__(256) knn_kernel(const float* __restrict__ pos1,
                                                  const float* __restrict__ pos2) {
    __shared__ float4 sp[SS];   // (x, y, z, |p|^2)
    int b = blockIdx.y;
    const float* p2 = pos2 + (size_t)b * 3 * SS;
    for (int s = threadIdx.x; s < SS; s += 256) {
        float x = p2[s], y = p2[SS + s], z = p2[2 * SS + s];
        sp[s] = make_float4(x, y, z, x * x + y * y + z * z);
    }
    __syncthreads();

    int wid = threadIdx.x >> 5, lane = threadIdx.x & 31;
    int n = blockIdx.x * 8 + wid;
    const float* p1 = pos1 + (size_t)b * 3 * NN;
    float x1 = p1[n], y1 = p1[NN + n], z1 = p1[2 * NN + n];
    float n1 = x1 * x1 + y1 * y1 + z1 * z1;
    float nx = -2.0f * x1, ny = -2.0f * y1, nz = -2.0f * z1;

    float d0 = CUDART_INF_F, d1 = CUDART_INF_F, d2v = CUDART_INF_F;
    int i0 = 0x7fffffff, i1 = 0x7fffffff, i2 = 0x7fffffff;

    for (int s = lane; s < SS; s += 32) {
        float4 p = sp[s];
        float d = fmaf(nx, p.x, fmaf(ny, p.y, fmaf(nz, p.z, p.w + n1)));
        top3_insert(d, s, d0, d1, d2v, i0, i1, i2);
    }
    // warp tree merge (snapshot before insert)
    for (int off = 16; off; off >>= 1) {
        float od0 = __shfl_down_sync(0xffffffffu, d0, off);
        float od1 = __shfl_down_sync(0xffffffffu, d1, off);
        float od2 = __shfl_down_sync(0xffffffffu, d2v, off);
        int   oi0 = __shfl_down_sync(0xffffffffu, i0, off);
        int   oi1 = __shfl_down_sync(0xffffffffu, i1, off);
        int   oi2 = __shfl_down_sync(0xffffffffu, i2, off);
        top3_insert(od0, oi0, d0, d1, d2v, i0, i1, i2);
        top3_insert(od1, oi1, d0, d1, d2v, i0, i1, i2);
        top3_insert(od2, oi2, d0, d1, d2v, i0, i1, i2);
    }
    if (lane == 0) {
        float w0 = 1.0f / fmaxf(d0, 1e-10f);
        float w1 = 1.0f / fmaxf(d1, 1e-10f);
        float w2 = 1.0f / fmaxf(d2v, 1e-10f);
        float ws = w0 + w1 + w2;
        int base = (b * NN + n) * 3;
        g_w[base + 0] = w0 / ws;  g_idx[base + 0] = i0;
        g_w[base + 1] = w1 / ws;  g_idx[base + 1] = i1;
        g_w[base + 2] = w2 / ws;  g_idx[base + 2] = i2;
    }
}

// ---------------- interpolation gather: block per (b, channel) ----------------
__global__ void __launch_bounds__(256) interp_kernel(const float* __restrict__ feature2) {
    __shared__ float row[SS];
    int c = blockIdx.y, b = blockIdx.z;
    const float* f2 = feature2 + ((size_t)b * D2 + c) * SS;
    for (int s = threadIdx.x; s < SS; s += 256) row[s] = f2[s];
    __syncthreads();
    int n = blockIdx.x * 256 + threadIdx.x;
    int base = (b * NN + n) * 3;
    float w0 = g_w[base], w1 = g_w[base + 1], w2 = g_w[base + 2];
    int   j0 = g_idx[base], j1 = g_idx[base + 1], j2 = g_idx[base + 2];
    float v = fmaf(w2, row[j2], fmaf(w1, row[j1], w0 * row[j0]));
    g_X[((size_t)b * CIN + c) * NN + n] = v;
}

// ---------------- concat: copy feature1 into rows [256, 384) ----------------
__global__ void __launch_bounds__(256) copyf1_kernel(const float* __restrict__ f1) {
    int i = blockIdx.x * 256 + threadIdx.x;              // over BB*D1*NN/4 float4s
    const int per_b = D1 * NN / 4;
    int b = i / per_b, r = i - b * per_b;
    const float4* src = (const float4*)f1;
    float4* dst = (float4*)g_X;
    dst[(size_t)b * (CIN * NN / 4) + (D2 * NN / 4) + r] = src[i];
}

// ---------------- SGEMM: C[256][8192] = W[256][K] @ X[K][8192] + bias ----------------
// MODE 0: X = g_X (stride CIN*NN), C = g_Y (stride CMID*NN)
// MODE 1: X = g_Y (stride CMID*NN), C = g_X (stride COUT*NN)
template <int K, int MODE>
__global__ void __launch_bounds__(256) gemm_kernel(const float* __restrict__ W,
                                                   const float* __restrict__ bias) {
    __shared__ float Ws[16][64];
    __shared__ float Xs[16][128];
    int b = blockIdx.z;
    const float* Xb = (MODE == 0) ? (g_X + (size_t)b * CIN * NN)
                                  : (g_Y + (size_t)b * CMID * NN);
    float* Cb       = (MODE == 0) ? (g_Y + (size_t)b * CMID * NN)
                                  : (g_X + (size_t)b * COUT * NN);
    int m0 = blockIdx.y * 64;
    int n0 = blockIdx.x * 128;
    int tid = threadIdx.x;
    int ty = tid >> 4, tx = tid & 15;

    float acc[4][8];
#pragma unroll
    for (int i = 0; i < 4; i++)
#pragma unroll
        for (int j = 0; j < 8; j++) acc[i][j] = 0.0f;

    int wm = tid >> 2;            // 0..63
    int wk = (tid & 3) * 4;       // 0,4,8,12
    int xk = tid >> 5;            // 0..7
    int xn = (tid & 31) * 4;      // 0..124

    for (int k0 = 0; k0 < K; k0 += 16) {
        float4 wv = *(const float4*)&W[(size_t)(m0 + wm) * K + k0 + wk];
        Ws[wk + 0][wm] = wv.x; Ws[wk + 1][wm] = wv.y;
        Ws[wk + 2][wm] = wv.z; Ws[wk + 3][wm] = wv.w;
        float4 xv0 = *(const float4*)&Xb[(size_t)(k0 + xk) * NN + n0 + xn];
        float4 xv1 = *(const float4*)&Xb[(size_t)(k0 + xk + 8) * NN + n0 + xn];
        *(float4*)&Xs[xk][xn]     = xv0;
        *(float4*)&Xs[xk + 8][xn] = xv1;
        __syncthreads();
#pragma unroll
        for (int k = 0; k < 16; k++) {
            float4 a  = *(const float4*)&Ws[k][ty * 4];
            float4 bl = *(const float4*)&Xs[k][tx * 8];
            float4 bh = *(const float4*)&Xs[k][tx * 8 + 4];
            float av[4] = {a.x, a.y, a.z, a.w};
            float bv[8] = {bl.x, bl.y, bl.z, bl.w, bh.x, bh.y, bh.z, bh.w};
#pragma unroll
            for (int i = 0; i < 4; i++)
#pragma unroll
                for (int j = 0; j < 8; j++)
                    acc[i][j] = fmaf(av[i], bv[j], acc[i][j]);
        }
        __syncthreads();
    }
#pragma unroll
    for (int i = 0; i < 4; i++) {
        float bi = bias[m0 + ty * 4 + i];
        float4 o0 = make_float4(acc[i][0] + bi, acc[i][1] + bi, acc[i][2] + bi, acc[i][3] + bi);
        float4 o1 = make_float4(acc[i][4] + bi, acc[i][5] + bi, acc[i][6] + bi, acc[i][7] + bi);
        float* cp = &Cb[(size_t)(m0 + ty * 4 + i) * NN + n0 + tx * 8];
        *(float4*)cp       = o0;
        *(float4*)(cp + 4) = o1;
    }
}

// ---------------- BN stats: block per channel ----------------
template <int MODE>
__global__ void __launch_bounds__(256) stats_kernel(const float* __restrict__ gma,
                                                    const float* __restrict__ bet) {
    int o = blockIdx.x;
    int tid = threadIdx.x;
    double s = 0.0, s2 = 0.0;
    for (int b = 0; b < BB; b++) {
        const float* p = ((MODE == 0) ? g_Y : g_X) + ((size_t)b * CMID + o) * NN;
        for (int n = tid; n < NN; n += 256) {
            float v = p[n];
            s += v; s2 += (double)v * v;
        }
    }
    __shared__ double sh[256], sh2[256];
    sh[tid] = s; sh2[tid] = s2;
    __syncthreads();
    for (int off = 128; off; off >>= 1) {
        if (tid < off) { sh[tid] += sh[tid + off]; sh2[tid] += sh2[tid + off]; }
        __syncthreads();
    }
    if (tid == 0) {
        const double M = (double)BB * NN;
        double m = sh[0] / M;
        double var = sh2[0] / M - m * m;
        float sc = gma[o] * rsqrtf((float)var + 1e-5f);
        g_scale[o] = sc;
        g_shift[o] = bet[o] - (float)m * sc;
    }
}

// ---------------- BN apply + ReLU ----------------
// MODE 0: g_Y -> g_Y (in place).  MODE 1: g_X -> out
template <int MODE>
__global__ void __launch_bounds__(256) bnrelu_kernel(float* __restrict__ out) {
    int i = blockIdx.x * 256 + threadIdx.x;   // float4 index, rows of NN/4=2048
    int o = (i >> 11) & 255;
    float sc = g_scale[o], sf = g_shift[o];
    const float4* in4 = (const float4*)((MODE == 0) ? g_Y : g_X);
    float4* out4 = (MODE == 0) ? (float4*)g_Y : (float4*)out;
    float4 v = in4[i];
    v.x = fmaxf(fmaf(v.x, sc, sf), 0.0f);
    v.y = fmaxf(fmaf(v.y, sc, sf), 0.0f);
    v.z = fmaxf(fmaf(v.z, sc, sf), 0.0f);
    v.w = fmaxf(fmaf(v.w, sc, sf), 0.0f);
    out4[i] = v;
}

// ---------------- launch ----------------
extern "C" void kernel_launch(void* const* d_in, const int* in_sizes, int n_in,
                              void* d_out, int out_size) {
    const float* pos1 = (const float*)d_in[0];
    const float* pos2 = (const float*)d_in[1];
    const float* f1   = (const float*)d_in[2];
    const float* f2   = (const float*)d_in[3];
    const float* W1   = (const float*)d_in[4];
    const float* b1   = (const float*)d_in[5];
    const float* g1   = (const float*)d_in[6];
    const float* be1  = (const float*)d_in[7];
    const float* W2   = (const float*)d_in[8];
    const float* b2   = (const float*)d_in[9];
    const float* g2   = (const float*)d_in[10];
    const float* be2  = (const float*)d_in[11];
    float* out = (float*)d_out;

    knn_kernel<<<dim3(NN / 8, BB), 256>>>(pos1, pos2);
    interp_kernel<<<dim3(NN / 256, D2, BB), 256>>>(f2);
    copyf1_kernel<<<(BB * D1 * NN / 4) / 256, 256>>>(f1);

    gemm_kernel<CIN, 0><<<dim3(NN / 128, CMID / 64, BB), 256>>>(W1, b1);
    stats_kernel<0><<<CMID, 256>>>(g1, be1);
    bnrelu_kernel<0><<<(BB * CMID * NN / 4) / 256, 256>>>(nullptr);

    gemm_kernel<CMID, 1><<<dim3(NN / 128, COUT / 64, BB), 256>>>(W2, b2);
    stats_kernel<1><<<COUT, 256>>>(g2, be2);
    bnrelu_kernel<1><<<(BB * COUT * NN / 4) / 256, 256>>>(out);
}

// round 6
// speedup vs baseline: 2.3702x; 2.3702x over previous
#include <cuda_runtime.h>
#include <cuda_bf16.h>
#include <math_constants.h>
#include <cstdint>

#define BB   4
#define NN   8192
#define SS   2048
#define D1   128
#define D2   256
#define CIN  384
#define CMID 256
#define COUT 256
#define NT   (NN / 128)   // 64 n-tiles

// ---------------- scratch ----------------
__device__ float g_X[(size_t)BB * NN * CIN];   // [b][n][c] concat input; reused as Y2 [b][n][256]
__device__ float g_Y[(size_t)BB * NN * CMID];  // GEMM1 out [b][n][c]
__device__ float g_F2T[(size_t)BB * SS * D2];  // feature2 transposed [b][s][c]
__device__ float g_w[BB * NN * 3];
__device__ int   g_idx[BB * NN * 3];
__device__ float g_scale[CMID];
__device__ float g_shift[CMID];
__device__ float g_psum[256 * 256];            // slot = b*NT + n-tile
__device__ float g_psq[256 * 256];

// ---------------- helpers ----------------
__device__ __forceinline__ uint32_t smem_u32(const void* p) {
    uint32_t a;
    asm("{ .reg .u64 t; cvta.to.shared.u64 t, %1; cvt.u32.u64 %0, t; }" : "=r"(a) : "l"(p));
    return a;
}
__device__ __forceinline__ void ldm_x4(uint32_t addr, uint32_t* f) {
    asm volatile("ldmatrix.sync.aligned.m8n8.x4.shared.b16 {%0,%1,%2,%3}, [%4];"
                 : "=r"(f[0]), "=r"(f[1]), "=r"(f[2]), "=r"(f[3]) : "r"(addr));
}
__device__ __forceinline__ void mma16816(float* c, const uint32_t* a, const uint32_t* b) {
    asm volatile("mma.sync.aligned.m16n8k16.row.col.f32.bf16.bf16.f32 "
                 "{%0,%1,%2,%3},{%4,%5,%6,%7},{%8,%9},{%0,%1,%2,%3};"
                 : "+f"(c[0]), "+f"(c[1]), "+f"(c[2]), "+f"(c[3])
                 : "r"(a[0]), "r"(a[1]), "r"(a[2]), "r"(a[3]), "r"(b[0]), "r"(b[1]));
}

// ---------------- 3-NN ----------------
__device__ __forceinline__ void top3_insert(float d, int i,
                                            float& d0, float& d1, float& d2v,
                                            int& i0, int& i1, int& i2) {
    bool b2 = (d < d2v) || (d == d2v && i < i2);
    if (!b2) return;
    bool b1 = (d < d1) || (d == d1 && i < i1);
    bool b0 = (d < d0) || (d == d0 && i < i0);
    if (b0)      { d2v = d1; i2 = i1; d1 = d0; i1 = i0; d0 = d;  i0 = i; }
    else if (b1) { d2v = d1; i2 = i1; d1 = d;  i1 = i; }
    else         { d2v = d;  i2 = i; }
}

__global__ void __launch_bounds__(256) knn_kernel(const float* __restrict__ pos1,
                                                  const float* __restrict__ pos2) {
    __shared__ float4 sp[SS];
    int b = blockIdx.y;
    const float* p2 = pos2 + (size_t)b * 3 * SS;
    for (int s = threadIdx.x; s < SS; s += 256) {
        float x = p2[s], y = p2[SS + s], z = p2[2 * SS + s];
        sp[s] = make_float4(x, y, z, x * x + y * y + z * z);
    }
    __syncthreads();
    int wid = threadIdx.x >> 5, lane = threadIdx.x & 31;
    int n = blockIdx.x * 8 + wid;
    const float* p1 = pos1 + (size_t)b * 3 * NN;
    float x1 = p1[n], y1 = p1[NN + n], z1 = p1[2 * NN + n];
    float n1 = x1 * x1 + y1 * y1 + z1 * z1;
    float nx = -2.0f * x1, ny = -2.0f * y1, nz = -2.0f * z1;
    float d0 = CUDART_INF_F, d1 = CUDART_INF_F, d2v = CUDART_INF_F;
    int i0 = 0x7fffffff, i1 = 0x7fffffff, i2 = 0x7fffffff;
    for (int s = lane; s < SS; s += 32) {
        float4 p = sp[s];
        float d = fmaf(nx, p.x, fmaf(ny, p.y, fmaf(nz, p.z, p.w + n1)));
        top3_insert(d, s, d0, d1, d2v, i0, i1, i2);
    }
    for (int off = 16; off; off >>= 1) {
        float od0 = __shfl_down_sync(0xffffffffu, d0, off);
        float od1 = __shfl_down_sync(0xffffffffu, d1, off);
        float od2 = __shfl_down_sync(0xffffffffu, d2v, off);
        int   oi0 = __shfl_down_sync(0xffffffffu, i0, off);
        int   oi1 = __shfl_down_sync(0xffffffffu, i1, off);
        int   oi2 = __shfl_down_sync(0xffffffffu, i2, off);
        top3_insert(od0, oi0, d0, d1, d2v, i0, i1, i2);
        top3_insert(od1, oi1, d0, d1, d2v, i0, i1, i2);
        top3_insert(od2, oi2, d0, d1, d2v, i0, i1, i2);
    }
    if (lane == 0) {
        float w0 = 1.0f / fmaxf(d0, 1e-10f);
        float w1 = 1.0f / fmaxf(d1, 1e-10f);
        float w2 = 1.0f / fmaxf(d2v, 1e-10f);
        float ws = w0 + w1 + w2;
        int base = (b * NN + n) * 3;
        g_w[base + 0] = w0 / ws;  g_idx[base + 0] = i0;
        g_w[base + 1] = w1 / ws;  g_idx[base + 1] = i1;
        g_w[base + 2] = w2 / ws;  g_idx[base + 2] = i2;
    }
}

// ---------------- transpose feature2 -> g_F2T [b][s][c] ----------------
__global__ void __launch_bounds__(256) tr_f2_kernel(const float* __restrict__ f2) {
    __shared__ float t[32][33];
    int b = blockIdx.z, c0 = blockIdx.y * 32, s0 = blockIdx.x * 32;
    int tx = threadIdx.x & 31, ty = threadIdx.x >> 5;
#pragma unroll
    for (int r = 0; r < 4; r++) {
        int i = ty + r * 8;
        t[i][tx] = f2[((size_t)b * D2 + c0 + i) * SS + s0 + tx];
    }
    __syncthreads();
#pragma unroll
    for (int r = 0; r < 4; r++) {
        int i = ty + r * 8;
        g_F2T[((size_t)b * SS + s0 + i) * 256 + c0 + tx] = t[tx][i];
    }
}

// ---------------- transpose feature1 into g_X cols [256,384) ----------------
__global__ void __launch_bounds__(256) tr_f1_kernel(const float* __restrict__ f1) {
    __shared__ float t[32][33];
    int b = blockIdx.z, c0 = blockIdx.y * 32, n0 = blockIdx.x * 32;
    int tx = threadIdx.x & 31, ty = threadIdx.x >> 5;
#pragma unroll
    for (int r = 0; r < 4; r++) {
        int i = ty + r * 8;
        t[i][tx] = f1[((size_t)b * D1 + c0 + i) * NN + n0 + tx];
    }
    __syncthreads();
#pragma unroll
    for (int r = 0; r < 4; r++) {
        int i = ty + r * 8;
        g_X[((size_t)b * NN + n0 + i) * CIN + 256 + c0 + tx] = t[tx][i];
    }
}

// ---------------- interp: thread = channel, block = 32 points ----------------
__global__ void __launch_bounds__(256) interp_kernel() {
    __shared__ int   sj[32 * 3];
    __shared__ float sw_[32 * 3];
    int b = blockIdx.y, n0 = blockIdx.x * 32;
    int tid = threadIdx.x;
    if (tid < 96) {
        int base = (b * NN + n0) * 3;
        sj[tid]  = g_idx[base + tid];
        sw_[tid] = g_w[base + tid];
    }
    __syncthreads();
    const float* f2t = g_F2T + (size_t)b * SS * 256;
#pragma unroll 4
    for (int p = 0; p < 32; p++) {
        int   j0 = sj[p * 3], j1 = sj[p * 3 + 1], j2 = sj[p * 3 + 2];
        float w0 = sw_[p * 3], w1 = sw_[p * 3 + 1], w2 = sw_[p * 3 + 2];
        float v = fmaf(w2, f2t[(size_t)j2 * 256 + tid],
                  fmaf(w1, f2t[(size_t)j1 * 256 + tid],
                       w0 * f2t[(size_t)j0 * 256 + tid]));
        g_X[((size_t)b * NN + n0 + p) * CIN + tid] = v;
    }
}

// ---------------- bf16-split HMMA GEMM ----------------
// out[n][m] = sum_k B[n][k] * W[m][k] + bias[m], stored [n][c].
// MODE 0: B = g_X (stride CIN), out = g_Y.  MODE 1: B = relu(bn1(g_Y)) (stride 256), out = g_X.
// smem tiles: 128 rows x 32 bf16, row stride 40 elems (80B) -> ldmatrix conflict-free.
#define RS 40

template <int K, int MODE>
__global__ void __launch_bounds__(256) gemm_tc(const float* __restrict__ W,
                                               const float* __restrict__ bias) {
    __shared__ __align__(16) uint16_t sAhi[128 * RS];
    __shared__ __align__(16) uint16_t sAlo[128 * RS];
    __shared__ __align__(16) uint16_t sBhi[128 * RS];
    __shared__ __align__(16) uint16_t sBlo[128 * RS];
    __shared__ float sc_s[256], sf_s[256];

    int tid = threadIdx.x, wid = tid >> 5, lane = tid & 31;
    int b = blockIdx.z, m0 = blockIdx.y * 128, n0 = blockIdx.x * 128;
    int wm = wid >> 2, wn = wid & 3;     // warp tile: (wm*64, wn*32)

    if (MODE) { sc_s[tid] = g_scale[tid]; sf_s[tid] = g_shift[tid]; }

    const float* Bsrc = MODE ? (g_Y + (size_t)b * NN * 256)
                             : (g_X + (size_t)b * NN * CIN);
    const int bstride = MODE ? 256 : CIN;

    const int r  = tid >> 1;          // tile row 0..127
    const int kq = (tid & 1) * 16;    // k sub-offset (floats)

    uint32_t uAhi = smem_u32(sAhi), uAlo = smem_u32(sAlo);
    uint32_t uBhi = smem_u32(sBhi), uBlo = smem_u32(sBlo);

    // ldmatrix per-lane addresses (element offsets)
    int arow = wm * 64 + (lane & 15);                     // + mi*16
    int acol = (lane >> 4) * 8;                           // + kk*16
    int brow = wn * 32 + (lane & 7) + ((lane >> 4) << 3); // + nb*16
    int bcol = ((lane >> 3) & 1) * 8;                     // + kk*16
    uint32_t aoff = (uint32_t)(arow * RS + acol) * 2;
    uint32_t boff = (uint32_t)(brow * RS + bcol) * 2;

    float acc[4][4][4];
#pragma unroll
    for (int i = 0; i < 4; i++)
#pragma unroll
        for (int j = 0; j < 4; j++)
#pragma unroll
            for (int q = 0; q < 4; q++) acc[i][j][q] = 0.0f;

    const int NCH = K / 32;
    for (int c = 0; c < NCH; c++) {
        // ---- load + split tiles ----
        {
            const float* srcA = W + (size_t)(m0 + r) * K + c * 32 + kq;
            uint32_t hv[8], lv[8];
#pragma unroll
            for (int j = 0; j < 4; j++) {
                float4 v = *(const float4*)(srcA + j * 4);
                __nv_bfloat162 h0 = __floats2bfloat162_rn(v.x, v.y);
                __nv_bfloat162 h1 = __floats2bfloat162_rn(v.z, v.w);
                float lx = v.x - __low2float(h0),  ly = v.y - __high2float(h0);
                float lz = v.z - __low2float(h1),  lw = v.w - __high2float(h1);
                __nv_bfloat162 l0 = __floats2bfloat162_rn(lx, ly);
                __nv_bfloat162 l1 = __floats2bfloat162_rn(lz, lw);
                hv[j * 2] = *(uint32_t*)&h0; hv[j * 2 + 1] = *(uint32_t*)&h1;
                lv[j * 2] = *(uint32_t*)&l0; lv[j * 2 + 1] = *(uint32_t*)&l1;
            }
            uint16_t* dh = &sAhi[r * RS + kq];
            uint16_t* dl = &sAlo[r * RS + kq];
            *(uint4*)dh       = make_uint4(hv[0], hv[1], hv[2], hv[3]);
            *(uint4*)(dh + 8) = make_uint4(hv[4], hv[5], hv[6], hv[7]);
            *(uint4*)dl       = make_uint4(lv[0], lv[1], lv[2], lv[3]);
            *(uint4*)(dl + 8) = make_uint4(lv[4], lv[5], lv[6], lv[7]);
        }
        {
            const float* srcB = Bsrc + (size_t)(n0 + r) * bstride + c * 32 + kq;
            int kb = c * 32 + kq;
            uint32_t hv[8], lv[8];
#pragma unroll
            for (int j = 0; j < 4; j++) {
                float4 v = *(const float4*)(srcB + j * 4);
                if (MODE) {
                    int k = kb + j * 4;
                    v.x = fmaxf(fmaf(v.x, sc_s[k + 0], sf_s[k + 0]), 0.0f);
                    v.y = fmaxf(fmaf(v.y, sc_s[k + 1], sf_s[k + 1]), 0.0f);
                    v.z = fmaxf(fmaf(v.z, sc_s[k + 2], sf_s[k + 2]), 0.0f);
                    v.w = fmaxf(fmaf(v.w, sc_s[k + 3], sf_s[k + 3]), 0.0f);
                }
                __nv_bfloat162 h0 = __floats2bfloat162_rn(v.x, v.y);
                __nv_bfloat162 h1 = __floats2bfloat162_rn(v.z, v.w);
                float lx = v.x - __low2float(h0),  ly = v.y - __high2float(h0);
                float lz = v.z - __low2float(h1),  lw = v.w - __high2float(h1);
                __nv_bfloat162 l0 = __floats2bfloat162_rn(lx, ly);
                __nv_bfloat162 l1 = __floats2bfloat162_rn(lz, lw);
                hv[j * 2] = *(uint32_t*)&h0; hv[j * 2 + 1] = *(uint32_t*)&h1;
                lv[j * 2] = *(uint32_t*)&l0; lv[j * 2 + 1] = *(uint32_t*)&l1;
            }
            uint16_t* dh = &sBhi[r * RS + kq];
            uint16_t* dl = &sBlo[r * RS + kq];
            *(uint4*)dh       = make_uint4(hv[0], hv[1], hv[2], hv[3]);
            *(uint4*)(dh + 8) = make_uint4(hv[4], hv[5], hv[6], hv[7]);
            *(uint4*)dl       = make_uint4(lv[0], lv[1], lv[2], lv[3]);
            *(uint4*)(dl + 8) = make_uint4(lv[4], lv[5], lv[6], lv[7]);
        }
        __syncthreads();

#pragma unroll
        for (int kk = 0; kk < 2; kk++) {
            uint32_t kadd = (uint32_t)(kk * 16) * 2;
            uint32_t ah[4][4], bf[4][2], tmp[4];
            // A hi frags
#pragma unroll
            for (int mi = 0; mi < 4; mi++)
                ldm_x4(uAhi + aoff + kadd + (uint32_t)(mi * 16 * RS) * 2, ah[mi]);
            // B hi frags
            ldm_x4(uBhi + boff + kadd, tmp);
            bf[0][0] = tmp[0]; bf[0][1] = tmp[1]; bf[1][0] = tmp[2]; bf[1][1] = tmp[3];
            ldm_x4(uBhi + boff + kadd + (uint32_t)(16 * RS) * 2, tmp);
            bf[2][0] = tmp[0]; bf[2][1] = tmp[1]; bf[3][0] = tmp[2]; bf[3][1] = tmp[3];
#pragma unroll
            for (int mi = 0; mi < 4; mi++)
#pragma unroll
                for (int ni = 0; ni < 4; ni++)
                    mma16816(acc[mi][ni], ah[mi], bf[ni]);
            // A lo x B hi
            uint32_t al[4][4];
#pragma unroll
            for (int mi = 0; mi < 4; mi++)
                ldm_x4(uAlo + aoff + kadd + (uint32_t)(mi * 16 * RS) * 2, al[mi]);
#pragma unroll
            for (int mi = 0; mi < 4; mi++)
#pragma unroll
                for (int ni = 0; ni < 4; ni++)
                    mma16816(acc[mi][ni], al[mi], bf[ni]);
            // A hi x B lo
            ldm_x4(uBlo + boff + kadd, tmp);
            bf[0][0] = tmp[0]; bf[0][1] = tmp[1]; bf[1][0] = tmp[2]; bf[1][1] = tmp[3];
            ldm_x4(uBlo + boff + kadd + (uint32_t)(16 * RS) * 2, tmp);
            bf[2][0] = tmp[0]; bf[2][1] = tmp[1]; bf[3][0] = tmp[2]; bf[3][1] = tmp[3];
#pragma unroll
            for (int mi = 0; mi < 4; mi++)
#pragma unroll
                for (int ni = 0; ni < 4; ni++)
                    mma16816(acc[mi][ni], ah[mi], bf[ni]);
        }
        __syncthreads();
    }

    // ---- epilogue: bias, stores, per-channel BN partials ----
    float* outp = MODE ? g_X : g_Y;   // [n][c] stride 256
    float* red  = (float*)sAhi;       // 128 ch x 4 wn sums
    float* red2 = red + 512;

#pragma unroll
    for (int mi = 0; mi < 4; mi++) {
#pragma unroll
        for (int rh = 0; rh < 2; rh++) {
            int ch = m0 + wm * 64 + mi * 16 + (lane >> 2) + rh * 8;
            float bi = __ldg(&bias[ch]);
            float s = 0.0f, s2 = 0.0f;
#pragma unroll
            for (int ni = 0; ni < 4; ni++) {
#pragma unroll
                for (int jc = 0; jc < 2; jc++) {
                    float v = acc[mi][ni][rh * 2 + jc] + bi;
                    s += v; s2 += v * v;
                    int n = n0 + wn * 32 + ni * 8 + (lane & 3) * 2 + jc;
                    outp[((size_t)b * NN + n) * 256 + ch] = v;
                }
            }
            s  += __shfl_xor_sync(0xffffffffu, s, 1);
            s  += __shfl_xor_sync(0xffffffffu, s, 2);
            s2 += __shfl_xor_sync(0xffffffffu, s2, 1);
            s2 += __shfl_xor_sync(0xffffffffu, s2, 2);
            if ((lane & 3) == 0) {
                int chl = ch - m0;
                red[chl * 4 + wn]  = s;
                red2[chl * 4 + wn] = s2;
            }
        }
    }
    __syncthreads();
    if (tid < 128) {
        float s  = red[tid * 4]  + red[tid * 4 + 1]  + red[tid * 4 + 2]  + red[tid * 4 + 3];
        float s2 = red2[tid * 4] + red2[tid * 4 + 1] + red2[tid * 4 + 2] + red2[tid * 4 + 3];
        int slot = b * NT + blockIdx.x;
        g_psum[slot * 256 + m0 + tid] = s;
        g_psq[slot * 256 + m0 + tid]  = s2;
    }
}

// ---------------- BN fit: reduce 256 partials per channel ----------------
__global__ void __launch_bounds__(128) bnfit_kernel(const float* __restrict__ gma,
                                                    const float* __restrict__ bet) {
    int o = blockIdx.x, tid = threadIdx.x;
    float s = 0.0f, s2 = 0.0f;
    for (int i = tid; i < 256; i += 128) {
        s  += g_psum[i * 256 + o];
        s2 += g_psq[i * 256 + o];
    }
    __shared__ float sh[128], sh2[128];
    sh[tid] = s; sh2[tid] = s2;
    __syncthreads();
    for (int off = 64; off; off >>= 1) {
        if (tid < off) { sh[tid] += sh[tid + off]; sh2[tid] += sh2[tid + off]; }
        __syncthreads();
    }
    if (tid == 0) {
        const float M = (float)(BB * NN);
        float m = sh[0] / M;
        float var = sh2[0] / M - m * m;
        float sc = gma[o] * rsqrtf(var + 1e-5f);
        g_scale[o] = sc;
        g_shift[o] = bet[o] - m * sc;
    }
}

// ---------------- final: BN2 + ReLU + transpose [n][c] -> out [c][n] ----------------
__global__ void __launch_bounds__(256) out_kernel(float* __restrict__ out) {
    __shared__ float t[32][33];
    int b = blockIdx.z, c0 = blockIdx.y * 32, n0 = blockIdx.x * 32;
    int tx = threadIdx.x & 31, ty = threadIdx.x >> 5;
#pragma unroll
    for (int r = 0; r < 4; r++) {
        int i = ty + r * 8;
        t[i][tx] = g_X[((size_t)b * NN + n0 + i) * 256 + c0 + tx];
    }
    __syncthreads();
#pragma unroll
    for (int r = 0; r < 4; r++) {
        int i = ty + r * 8;
        float sc = g_scale[c0 + i], sf = g_shift[c0 + i];
        out[((size_t)b * 256 + c0 + i) * NN + n0 + tx] =
            fmaxf(fmaf(t[tx][i], sc, sf), 0.0f);
    }
}

// ---------------- launch ----------------
extern "C" void kernel_launch(void* const* d_in, const int* in_sizes, int n_in,
                              void* d_out, int out_size) {
    const float* pos1 = (const float*)d_in[0];
    const float* pos2 = (const float*)d_in[1];
    const float* f1   = (const float*)d_in[2];
    const float* f2   = (const float*)d_in[3];
    const float* W1   = (const float*)d_in[4];
    const float* b1   = (const float*)d_in[5];
    const float* g1   = (const float*)d_in[6];
    const float* be1  = (const float*)d_in[7];
    const float* W2   = (const float*)d_in[8];
    const float* b2   = (const float*)d_in[9];
    const float* g2   = (const float*)d_in[10];
    const float* be2  = (const float*)d_in[11];
    float* out = (float*)d_out;

    knn_kernel<<<dim3(NN / 8, BB), 256>>>(pos1, pos2);
    tr_f2_kernel<<<dim3(SS / 32, D2 / 32, BB), 256>>>(f2);
    tr_f1_kernel<<<dim3(NN / 32, D1 / 32, BB), 256>>>(f1);
    interp_kernel<<<dim3(NN / 32, BB), 256>>>();

    gemm_tc<CIN, 0><<<dim3(NT, 2, BB), 256>>>(W1, b1);
    bnfit_kernel<<<256, 128>>>(g1, be1);

    gemm_tc<CMID, 1><<<dim3(NT, 2, BB), 256>>>(W2, b2);
    bnfit_kernel<<<256, 128>>>(g2, be2);

    out_kernel<<<dim3(NN / 32, 256 / 32, BB), 256>>>(out);
}